// round 6
// baseline (speedup 1.0000x reference)
#include <cuda_runtime.h>
#include <cuda_bf16.h>
#include <cstdint>

// LIF neuron forward scan over STEP=4 time steps.
// x:   [STEP, B, C, H, W] fp32  (default spatial = 64*128*32*32 = 8,388,608)
// out: [STEP, B, C, H, W] fp32, spike in {0,1}
//
// Per spatial position, t = 0..3:
//   mem = mem*0.25 + x_t;  spike = (mem > 0.5);  out_t = spike;  mem = spike ? 0 : mem
//
// Pure HBM streaming. Each thread handles 4 CONSECUTIVE float4 (64B) per
// plane -> each warp reads 2KB contiguous per plane, 16 front-batched
// LDG.128 per thread (MLP=16). Streaming cache hints (read-once/write-once).

#define LIF_DECAY 0.25f
#define LIF_STEP  4
#define VPT 4   // float4 per thread per plane

__device__ __forceinline__ void lif_scan4(const float4 xt[LIF_STEP], float4 o[LIF_STEP])
{
    float4 mem = make_float4(0.f, 0.f, 0.f, 0.f);
#pragma unroll
    for (int t = 0; t < LIF_STEP; ++t) {
        mem.x = fmaf(mem.x, LIF_DECAY, xt[t].x);
        o[t].x = (mem.x > 0.5f) ? 1.0f : 0.0f;
        mem.x  = (mem.x > 0.5f) ? 0.0f : mem.x;

        mem.y = fmaf(mem.y, LIF_DECAY, xt[t].y);
        o[t].y = (mem.y > 0.5f) ? 1.0f : 0.0f;
        mem.y  = (mem.y > 0.5f) ? 0.0f : mem.y;

        mem.z = fmaf(mem.z, LIF_DECAY, xt[t].z);
        o[t].z = (mem.z > 0.5f) ? 1.0f : 0.0f;
        mem.z  = (mem.z > 0.5f) ? 0.0f : mem.z;

        mem.w = fmaf(mem.w, LIF_DECAY, xt[t].w);
        o[t].w = (mem.w > 0.5f) ? 1.0f : 0.0f;
        mem.w  = (mem.w > 0.5f) ? 0.0f : mem.w;
    }
}

// Fast path: n4 divisible by VPT*blockDim handled via exact grid + guard.
__global__ __launch_bounds__(256)
void LIFAct_17051020165839_vec(const float4* __restrict__ x,
                               float4* __restrict__ out,
                               int n4)  // float4 count per time step
{
    // Thread handles VPT consecutive float4 per plane.
    const int base = (blockIdx.x * blockDim.x + threadIdx.x) * VPT;
    if (base >= n4) return;

    if (base + VPT <= n4) {
        // Front-batch all 16 loads (4 groups x 4 planes), streaming.
        float4 xv[VPT][LIF_STEP];
#pragma unroll
        for (int g = 0; g < VPT; ++g)
#pragma unroll
            for (int t = 0; t < LIF_STEP; ++t)
                xv[g][t] = __ldcs(&x[(size_t)t * n4 + base + g]);

#pragma unroll
        for (int g = 0; g < VPT; ++g) {
            float4 o[LIF_STEP];
            lif_scan4(xv[g], o);
#pragma unroll
            for (int t = 0; t < LIF_STEP; ++t)
                __stcs(&out[(size_t)t * n4 + base + g], o[t]);
        }
    } else {
        // Ragged edge: per-float4 guard.
        for (int g = 0; g < VPT; ++g) {
            const int i = base + g;
            if (i >= n4) break;
            float4 xt[LIF_STEP], o[LIF_STEP];
#pragma unroll
            for (int t = 0; t < LIF_STEP; ++t)
                xt[t] = __ldcs(&x[(size_t)t * n4 + i]);
            lif_scan4(xt, o);
#pragma unroll
            for (int t = 0; t < LIF_STEP; ++t)
                __stcs(&out[(size_t)t * n4 + i], o[t]);
        }
    }
}

// Scalar tail for spatial sizes not divisible by 4 (not launched for the
// default shape).
__global__ __launch_bounds__(256)
void LIFAct_17051020165839_tail(const float* __restrict__ x,
                                float* __restrict__ out,
                                int per_step, int tail_start)
{
    const int i = tail_start + blockIdx.x * blockDim.x + threadIdx.x;
    if (i >= per_step) return;

    float mem = 0.0f;
#pragma unroll
    for (int t = 0; t < LIF_STEP; ++t) {
        mem = fmaf(mem, LIF_DECAY, __ldcs(&x[(size_t)t * per_step + i]));
        const bool s = (mem > 0.5f);
        __stcs(&out[(size_t)t * per_step + i], s ? 1.0f : 0.0f);
        mem = s ? 0.0f : mem;
    }
}

extern "C" void kernel_launch(void* const* d_in, const int* in_sizes, int n_in,
                              void* d_out, int out_size)
{
    const float* x = (const float*)d_in[0];
    float* out = (float*)d_out;

    const int total = in_sizes[0];           // STEP * spatial
    const int per_step = total / LIF_STEP;   // spatial element count
    const int n4 = per_step / 4;             // full float4 chunks per time step

    if (n4 > 0) {
        const int threads = 256;
        const int f4_per_block = threads * VPT;
        int blocks = (n4 + f4_per_block - 1) / f4_per_block;
        LIFAct_17051020165839_vec<<<blocks, threads>>>(
            (const float4*)x, (float4*)out, n4);
    }

    const int tail_start = n4 * 4;
    const int tail = per_step - tail_start;
    if (tail > 0) {
        const int threads = 256;
        const int blocks = (tail + threads - 1) / threads;
        LIFAct_17051020165839_tail<<<blocks, threads>>>(x, out, per_step, tail_start);
    }
}

// round 10
// speedup vs baseline: 1.3363x; 1.3363x over previous
#include <cuda_runtime.h>
#include <cuda_bf16.h>
#include <cstdint>

// LIF neuron forward scan over STEP=4 time steps.
// x:   [STEP, B, C, H, W] fp32  (default spatial = 64*128*32*32 = 8,388,608)
// out: [STEP, B, C, H, W] fp32, spike in {0,1}
//
// Per spatial position, t = 0..3:
//   mem = mem*0.25 + x_t;  spike = (mem > 0.5);  out_t = spike;  mem = spike ? 0 : mem
//
// Pure HBM streaming. Blackwell 256-bit vector ld/st (LDG.E.256 / STG.E.256):
// each thread handles 8 consecutive floats (32B) per plane; one warp
// instruction covers 1KB fully contiguous. 4 front-batched v8 loads per
// thread (one per plane), streaming cache hints.

#define LIF_DECAY 0.25f
#define LIF_STEP  4

__device__ __forceinline__ void ldg256_cs(const float* p, float r[8])
{
    asm volatile("ld.global.cs.v8.f32 {%0,%1,%2,%3,%4,%5,%6,%7}, [%8];"
                 : "=f"(r[0]), "=f"(r[1]), "=f"(r[2]), "=f"(r[3]),
                   "=f"(r[4]), "=f"(r[5]), "=f"(r[6]), "=f"(r[7])
                 : "l"(p));
}

__device__ __forceinline__ void stg256_cs(float* p, const float r[8])
{
    asm volatile("st.global.cs.v8.f32 [%0], {%1,%2,%3,%4,%5,%6,%7,%8};"
                 :: "l"(p),
                    "f"(r[0]), "f"(r[1]), "f"(r[2]), "f"(r[3]),
                    "f"(r[4]), "f"(r[5]), "f"(r[6]), "f"(r[7])
                 : "memory");
}

__global__ __launch_bounds__(256)
void LIFAct_17051020165839_vec(const float* __restrict__ x,
                               float* __restrict__ out,
                               int n8)  // 8-float chunks per time step
{
    const int i = blockIdx.x * blockDim.x + threadIdx.x;
    if (i >= n8) return;
    const size_t base = (size_t)i * 8;
    const size_t plane = (size_t)n8 * 8;

    // Front-batch 4 independent 256-bit loads (one per plane) -> MLP=4 v8.
    float xt[LIF_STEP][8];
#pragma unroll
    for (int t = 0; t < LIF_STEP; ++t)
        ldg256_cs(x + (size_t)t * plane + base, xt[t]);

    float mem[8];
#pragma unroll
    for (int e = 0; e < 8; ++e) mem[e] = 0.0f;

#pragma unroll
    for (int t = 0; t < LIF_STEP; ++t) {
        float o[8];
#pragma unroll
        for (int e = 0; e < 8; ++e) {
            mem[e] = fmaf(mem[e], LIF_DECAY, xt[t][e]);
            const bool s = (mem[e] > 0.5f);
            o[e]   = s ? 1.0f : 0.0f;
            mem[e] = s ? 0.0f : mem[e];
        }
        stg256_cs(out + (size_t)t * plane + base, o);
    }
}

// Scalar tail for spatial sizes not divisible by 8 (not launched for the
// default shape).
__global__ __launch_bounds__(256)
void LIFAct_17051020165839_tail(const float* __restrict__ x,
                                float* __restrict__ out,
                                int per_step, int tail_start)
{
    const int i = tail_start + blockIdx.x * blockDim.x + threadIdx.x;
    if (i >= per_step) return;

    float mem = 0.0f;
#pragma unroll
    for (int t = 0; t < LIF_STEP; ++t) {
        mem = fmaf(mem, LIF_DECAY, __ldcs(&x[(size_t)t * per_step + i]));
        const bool s = (mem > 0.5f);
        __stcs(&out[(size_t)t * per_step + i], s ? 1.0f : 0.0f);
        mem = s ? 0.0f : mem;
    }
}

extern "C" void kernel_launch(void* const* d_in, const int* in_sizes, int n_in,
                              void* d_out, int out_size)
{
    const float* x = (const float*)d_in[0];
    float* out = (float*)d_out;

    const int total = in_sizes[0];           // STEP * spatial
    const int per_step = total / LIF_STEP;   // spatial element count
    const int n8 = per_step / 8;             // 8-float chunks per time step

    if (n8 > 0) {
        const int threads = 256;
        const int blocks = (n8 + threads - 1) / threads;
        LIFAct_17051020165839_vec<<<blocks, threads>>>(x, out, n8);
    }

    const int tail_start = n8 * 8;
    const int tail = per_step - tail_start;
    if (tail > 0) {
        const int threads = 256;
        const int blocks = (tail + threads - 1) / threads;
        LIFAct_17051020165839_tail<<<blocks, threads>>>(x, out, per_step, tail_start);
    }
}